// round 2
// baseline (speedup 1.0000x reference)
#include <cuda_runtime.h>
#include <math.h>

#define C_IN 2048
#define HWD  1024
#define PN   2048     // B*H*W
#define BB   2
#define OC   256
#define EPSV 1e-5f

#define ROWS_B2 256
#define ROWS_B3 2560
#define ROWS_B4 4864
#define ROWS_OM 7168
#define M_REAL  7924
#define M_PAD   7936

// ---------------- scratch (static device globals; no allocation) ----------------
__device__ float g_Wcat[(long)M_PAD * C_IN];   // 65 MB packed A for GEMM1
__device__ float g_Xt[(long)C_IN * PN];        // 16.8 MB  X[c][p]
__device__ float g_D[(long)M_PAD * PN];        // 65 MB dense 1x1 responses
__device__ float g_OM[84 * PN];                // offset/mod conv results
__device__ float g_CAT[1280 * PN];             // concat buffer [ch][p]
__device__ float g_FOUT[OC * PN];              // fused output pre-BN
__device__ float g_GAP[BB * C_IN];
__device__ float g_PV[BB * OC];

// ---------------- packing ----------------
__global__ void pack_wcat(const float* w1, const float* w2, const float* w3, const float* w4,
                          const float* wo1, const float* wm1, const float* wo2, const float* wm2,
                          const float* wo3, const float* wm3, const float* wo4, const float* wm4) {
    long idx = (long)blockIdx.x * 256 + threadIdx.x;
    if (idx >= (long)M_PAD * C_IN) return;
    int r = (int)(idx / C_IN); int c = (int)(idx % C_IN);
    float v = 0.f;
    if (r < ROWS_B2) {
        v = w1[(long)r * C_IN + c];                              // [256,2048,1,1]
    } else if (r < ROWS_B3) {
        int rr = r - ROWS_B2; int t = rr >> 8; int o = rr & 255;
        v = w2[((long)o * C_IN + c) * 9 + t];
    } else if (r < ROWS_B4) {
        int rr = r - ROWS_B3; int t = rr >> 8; int o = rr & 255;
        v = w3[((long)o * C_IN + c) * 9 + t];
    } else if (r < ROWS_OM) {
        int rr = r - ROWS_B4; int t = rr >> 8; int o = rr & 255;
        v = w4[((long)o * C_IN + c) * 9 + t];
    } else if (r < M_REAL) {
        int rr = r - ROWS_OM; int m = rr / 9; int t = rr % 9;
        const float* src; int ml;
        if (m < 3)       { ml = m;      src = (ml < 2)  ? wo1 + (long)ml * C_IN * 9      : wm1 + (long)(ml - 2)  * C_IN * 9; }
        else if (m < 30) { ml = m - 3;  src = (ml < 18) ? wo2 + (long)ml * C_IN * 9      : wm2 + (long)(ml - 18) * C_IN * 9; }
        else if (m < 57) { ml = m - 30; src = (ml < 18) ? wo3 + (long)ml * C_IN * 9      : wm3 + (long)(ml - 18) * C_IN * 9; }
        else             { ml = m - 57; src = (ml < 18) ? wo4 + (long)ml * C_IN * 9      : wm4 + (long)(ml - 18) * C_IN * 9; }
        v = src[(long)c * 9 + t];
    }
    g_Wcat[idx] = v;
}

__global__ void pack_xt(const float* __restrict__ x) {
    int idx = blockIdx.x * 256 + threadIdx.x;
    if (idx >= C_IN * PN) return;
    int c = idx >> 11; int p = idx & 2047;
    int b = p >> 10; int yx = p & 1023;
    g_Xt[idx] = x[((long)b * C_IN + c) * HWD + yx];
}

// ---------------- generic SGEMM: C[MxN] = A[MxK] * B[KxN], row-major ----------------
template<int BM, int BN, int BK, int TM, int TN>
__global__ void sgemm(const float* __restrict__ A, const float* __restrict__ B,
                      float* __restrict__ Cc, int M, int N, int K) {
    __shared__ float As[BK * BM];
    __shared__ float Bs[BK * BN];
    const int NT = (BM / TM) * (BN / TN);   // 256
    const int tid = threadIdx.x;
    const int m0 = blockIdx.y * BM;
    const int n0 = blockIdx.x * BN;
    const int tx = tid % (BN / TN);
    const int ty = tid / (BN / TN);

    float acc[TM][TN];
    #pragma unroll
    for (int i = 0; i < TM; i++)
        #pragma unroll
        for (int j = 0; j < TN; j++) acc[i][j] = 0.f;

    for (int k0 = 0; k0 < K; k0 += BK) {
        for (int i4 = tid; i4 < BM * BK / 4; i4 += NT) {
            int row = i4 / (BK / 4);
            int cg  = i4 % (BK / 4);
            float4 v = make_float4(0.f, 0.f, 0.f, 0.f);
            if (m0 + row < M)
                v = *reinterpret_cast<const float4*>(A + (long)(m0 + row) * K + k0 + cg * 4);
            As[(cg * 4 + 0) * BM + row] = v.x;
            As[(cg * 4 + 1) * BM + row] = v.y;
            As[(cg * 4 + 2) * BM + row] = v.z;
            As[(cg * 4 + 3) * BM + row] = v.w;
        }
        for (int i4 = tid; i4 < BK * BN / 4; i4 += NT) {
            int kk  = i4 / (BN / 4);
            int col = (i4 % (BN / 4)) * 4;
            float4 v = *reinterpret_cast<const float4*>(B + (long)(k0 + kk) * N + n0 + col);
            *reinterpret_cast<float4*>(&Bs[kk * BN + col]) = v;
        }
        __syncthreads();
        #pragma unroll
        for (int kk = 0; kk < BK; kk++) {
            float af[TM], bf[TN];
            #pragma unroll
            for (int i = 0; i < TM; i++) af[i] = As[kk * BM + ty * TM + i];
            #pragma unroll
            for (int j = 0; j < TN; j++) bf[j] = Bs[kk * BN + tx * TN + j];
            #pragma unroll
            for (int i = 0; i < TM; i++)
                #pragma unroll
                for (int j = 0; j < TN; j++) acc[i][j] += af[i] * bf[j];
        }
        __syncthreads();
    }
    #pragma unroll
    for (int i = 0; i < TM; i++) {
        int m = m0 + ty * TM + i;
        if (m >= M) continue;
        #pragma unroll
        for (int j = 0; j < TN; j += 4) {
            *reinterpret_cast<float4*>(Cc + (long)m * N + n0 + tx * TN + j) =
                make_float4(acc[i][j], acc[i][j + 1], acc[i][j + 2], acc[i][j + 3]);
        }
    }
}

// ---------------- combine the 9 shifted 1x1 responses into 3x3-conv results ----------------
__global__ void om_combine() {
    int idx = blockIdx.x * 256 + threadIdx.x;
    if (idx >= 84 * PN) return;
    int m = idx >> 11; int p = idx & 2047;
    int b = p >> 10; int yx = p & 1023; int y = yx >> 5; int x = yx & 31;
    const float* E = g_D + (long)(ROWS_OM + m * 9) * PN;
    float s = 0.f;
    #pragma unroll
    for (int t = 0; t < 9; t++) {
        int yy = y + t / 3 - 1; int xx = x + t % 3 - 1;
        if (yy >= 0 && yy < 32 && xx >= 0 && xx < 32)
            s += E[(long)t * PN + b * HWD + yy * 32 + xx];
    }
    g_OM[idx] = s;
}

// ---------------- deformable sampling + modulation (bilinear on dense D) ----------------
__global__ void deform_combine() {
    const int kk_[4]   = {1, 3, 3, 3};
    const int dil_[4]  = {1, 6, 12, 18};
    const int pad_[4]  = {0, 6, 12, 18};
    const int drow_[4] = {0, ROWS_B2, ROWS_B3, ROWS_B4};
    const int mb_[4]   = {0, 3, 30, 57};

    int br = blockIdx.y;
    int idx = blockIdx.x * 256 + threadIdx.x;   // 524288 per branch
    int o = idx >> 11; int p = idx & 2047;
    int b = p >> 10; int yx = p & 1023; int y = yx >> 5; int x = yx & 31;

    int k = kk_[br], dil = dil_[br], pad = pad_[br];
    int n = k * k;
    int hp = 32 + 2 * pad;
    float hpm1 = (float)(hp - 1);
    const float* OMB = g_OM + (long)mb_[br] * PN + p;
    const float* Db  = g_D + (long)(drow_[br] + o) * PN + b * HWD;

    float acc = 0.f;
    for (int t = 0; t < n; t++) {
        float offy = OMB[(long)t * PN];
        float offx = OMB[(long)(n + t) * PN];
        float modv = OMB[(long)(2 * n + t) * PN];
        modv = 1.f / (1.f + expf(-modv));
        float py = (float)(y + (t / k) * dil) + offy;
        float px = (float)(x + (t % k) * dil) + offx;
        py = fminf(fmaxf(py, 0.f), hpm1);
        px = fminf(fmaxf(px, 0.f), hpm1);
        float fy0 = floorf(py), fx0 = floorf(px);
        float wy = py - fy0, wx = px - fx0;
        int y0 = (int)fy0, x0 = (int)fx0;
        int y1 = min(y0 + 1, hp - 1), x1 = min(x0 + 1, hp - 1);
        const float* Dt = Db + (long)t * 256 * PN;

        float v00 = 0.f, v01 = 0.f, v10 = 0.f, v11 = 0.f;
        {
            int ry0 = y0 - pad, rx0 = x0 - pad, ry1 = y1 - pad, rx1 = x1 - pad;
            bool oy0 = (ry0 >= 0 && ry0 < 32), oy1 = (ry1 >= 0 && ry1 < 32);
            bool ox0 = (rx0 >= 0 && rx0 < 32), ox1 = (rx1 >= 0 && rx1 < 32);
            if (oy0 && ox0) v00 = Dt[ry0 * 32 + rx0];
            if (oy0 && ox1) v01 = Dt[ry0 * 32 + rx1];
            if (oy1 && ox0) v10 = Dt[ry1 * 32 + rx0];
            if (oy1 && ox1) v11 = Dt[ry1 * 32 + rx1];
        }
        float v = (1.f - wy) * ((1.f - wx) * v00 + wx * v01)
                +        wy  * ((1.f - wx) * v10 + wx * v11);
        acc += modv * v;
    }
    g_CAT[(long)(br * 256 + o) * PN + p] = acc;
}

// ---------------- reductions / BN ----------------
__device__ __forceinline__ float blockReduceSum(float v, float* sdata) {
    int tid = threadIdx.x;
    #pragma unroll
    for (int off = 16; off > 0; off >>= 1) v += __shfl_down_sync(0xffffffff, v, off);
    if ((tid & 31) == 0) sdata[tid >> 5] = v;
    __syncthreads();
    if (tid < 8) {
        float s = sdata[tid];
        #pragma unroll
        for (int off = 4; off > 0; off >>= 1) s += __shfl_down_sync(0xff, s, off);
        if (tid == 0) sdata[0] = s;
    }
    __syncthreads();
    float r = sdata[0];
    __syncthreads();
    return r;
}

__global__ void bn_relu_branches(const float* g1, const float* be1, const float* g2, const float* be2,
                                 const float* g3, const float* be3, const float* g4, const float* be4) {
    __shared__ float sdata[8];
    int ch = blockIdx.x;           // 0..1023
    int br = ch >> 8; int c = ch & 255;
    const float* gp = br == 0 ? g1 : br == 1 ? g2 : br == 2 ? g3 : g4;
    const float* bp = br == 0 ? be1 : br == 1 ? be2 : br == 2 ? be3 : be4;
    float* row = g_CAT + (long)ch * PN;
    int tid = threadIdx.x;
    float v[8]; float s = 0.f;
    #pragma unroll
    for (int i = 0; i < 8; i++) { v[i] = row[tid + i * 256]; s += v[i]; }
    s = blockReduceSum(s, sdata);
    float mu = s / 2048.f;
    float q = 0.f;
    #pragma unroll
    for (int i = 0; i < 8; i++) { float d = v[i] - mu; q += d * d; }
    q = blockReduceSum(q, sdata);
    float inv = rsqrtf(q / 2048.f + EPSV);
    float ga = gp[c], bb = bp[c];
    #pragma unroll
    for (int i = 0; i < 8; i++)
        row[tid + i * 256] = fmaxf((v[i] - mu) * inv * ga + bb, 0.f);
}

__global__ void bn_final(const float* gf, const float* bf) {
    __shared__ float sdata[8];
    int c = blockIdx.x;           // 0..255
    float* row = g_FOUT + (long)c * PN;
    int tid = threadIdx.x;
    float v[8]; float s = 0.f;
    #pragma unroll
    for (int i = 0; i < 8; i++) { v[i] = row[tid + i * 256]; s += v[i]; }
    s = blockReduceSum(s, sdata);
    float mu = s / 2048.f;
    float q = 0.f;
    #pragma unroll
    for (int i = 0; i < 8; i++) { float d = v[i] - mu; q += d * d; }
    q = blockReduceSum(q, sdata);
    float inv = rsqrtf(q / 2048.f + EPSV);
    float ga = gf[c], bb = bf[c];
    #pragma unroll
    for (int i = 0; i < 8; i++)
        row[tid + i * 256] = fmaxf((v[i] - mu) * inv * ga + bb, 0.f);
}

// ---------------- pooling branch ----------------
__global__ void gap_kernel(const float* __restrict__ x) {
    __shared__ float sdata[8];
    int bc = blockIdx.x;                       // b*2048 + c (contiguous layout)
    const float* px = x + (long)bc * HWD;
    float s = 0.f; int tid = threadIdx.x;
    for (int i = tid; i < HWD; i += 256) s += px[i];
    s = blockReduceSum(s, sdata);
    if (tid == 0) g_GAP[bc] = s / 1024.f;
}

__global__ void pool_fc_bn(const float* __restrict__ wpool, const float* gp, const float* bp) {
    __shared__ float sdata[8];
    __shared__ float sp0;
    int o = blockIdx.x; int tid = threadIdx.x;
    const float* wr = wpool + (long)o * C_IN;
    float s0 = 0.f, s1 = 0.f;
    for (int c = tid; c < C_IN; c += 256) {
        float w = wr[c];
        s0 += w * g_GAP[c];
        s1 += w * g_GAP[2048 + c];
    }
    s0 = blockReduceSum(s0, sdata);
    if (tid == 0) sp0 = s0;
    __syncthreads();
    s1 = blockReduceSum(s1, sdata);
    if (tid == 0) {
        float p0 = sp0, p1 = s1;
        float mu = 0.5f * (p0 + p1);
        float var = 0.5f * ((p0 - mu) * (p0 - mu) + (p1 - mu) * (p1 - mu));
        float inv = rsqrtf(var + EPSV);
        float ga = gp[o], be = bp[o];
        g_PV[o]       = fmaxf((p0 - mu) * inv * ga + be, 0.f);
        g_PV[256 + o] = fmaxf((p1 - mu) * inv * ga + be, 0.f);
    }
}

__global__ void pool_broadcast() {
    int idx = blockIdx.x * 256 + threadIdx.x;   // 256*2048
    if (idx >= OC * PN) return;
    int o = idx >> 11; int p = idx & 2047; int b = p >> 10;
    g_CAT[(long)(1024 + o) * PN + p] = g_PV[b * 256 + o];
}

// ---------------- final layout write ----------------
__global__ void writeout(float* __restrict__ out) {
    int idx = blockIdx.x * 256 + threadIdx.x;   // 2*256*1024
    int b = idx >> 18; int o = (idx >> 10) & 255; int yx = idx & 1023;
    out[idx] = g_FOUT[(long)o * PN + b * HWD + yx];
}

// ---------------- launcher ----------------
extern "C" void kernel_launch(void* const* d_in, const int* in_sizes, int n_in,
                              void* d_out, int out_size) {
    (void)in_sizes; (void)n_in; (void)out_size;
    const float* x    = (const float*)d_in[0];
    const float* wo1  = (const float*)d_in[1];
    const float* wm1  = (const float*)d_in[2];
    const float* w1   = (const float*)d_in[3];
    const float* g1   = (const float*)d_in[4];
    const float* b1   = (const float*)d_in[5];
    const float* wo2  = (const float*)d_in[6];
    const float* wm2  = (const float*)d_in[7];
    const float* w2   = (const float*)d_in[8];
    const float* g2   = (const float*)d_in[9];
    const float* b2   = (const float*)d_in[10];
    const float* wo3  = (const float*)d_in[11];
    const float* wm3  = (const float*)d_in[12];
    const float* w3   = (const float*)d_in[13];
    const float* g3   = (const float*)d_in[14];
    const float* b3   = (const float*)d_in[15];
    const float* wo4  = (const float*)d_in[16];
    const float* wm4  = (const float*)d_in[17];
    const float* w4   = (const float*)d_in[18];
    const float* g4   = (const float*)d_in[19];
    const float* b4   = (const float*)d_in[20];
    const float* wpool= (const float*)d_in[21];
    const float* gp   = (const float*)d_in[22];
    const float* bp   = (const float*)d_in[23];
    const float* wfuse= (const float*)d_in[24];
    const float* gf   = (const float*)d_in[25];
    const float* bf   = (const float*)d_in[26];
    float* out = (float*)d_out;

    void *pW = nullptr, *pX = nullptr, *pD = nullptr, *pCAT = nullptr, *pF = nullptr;
    cudaGetSymbolAddress(&pW, g_Wcat);
    cudaGetSymbolAddress(&pX, g_Xt);
    cudaGetSymbolAddress(&pD, g_D);
    cudaGetSymbolAddress(&pCAT, g_CAT);
    cudaGetSymbolAddress(&pF, g_FOUT);

    // 1. pack weights + input
    pack_wcat<<<(int)(((long)M_PAD * C_IN + 255) / 256), 256>>>(w1, w2, w3, w4,
                                                                wo1, wm1, wo2, wm2, wo3, wm3, wo4, wm4);
    pack_xt<<<(C_IN * PN + 255) / 256, 256>>>(x);

    // 2. one big dense GEMM: all taps of all deform branches + all offset/mod conv rows
    sgemm<128, 128, 8, 8, 8><<<dim3(PN / 128, M_PAD / 128), 256>>>(
        (const float*)pW, (const float*)pX, (float*)pD, M_PAD, PN, C_IN);

    // 3. offset/mod 3x3 shift-sum, then bilinear deformable combine
    om_combine<<<(84 * PN + 255) / 256, 256>>>();
    deform_combine<<<dim3(2048, 4), 256>>>();

    // 4. per-branch BN + relu (in place in CAT)
    bn_relu_branches<<<1024, 256>>>(g1, b1, g2, b2, g3, b3, g4, b4);

    // 5. pooling branch
    gap_kernel<<<BB * C_IN, 256>>>(x);
    pool_fc_bn<<<256, 256>>>(wpool, gp, bp);
    pool_broadcast<<<(OC * PN) / 256, 256>>>();

    // 6. fuse 1x1 conv + final BN + relu + NCHW writeout
    sgemm<64, 64, 8, 4, 4><<<dim3(PN / 64, OC / 64), 256>>>(
        wfuse, (const float*)pCAT, (float*)pF, OC, PN, 1280);
    bn_final<<<OC, 256>>>(gf, bf);
    writeout<<<(BB * OC * HWD) / 256, 256>>>(out);
}

// round 4
// speedup vs baseline: 3.1908x; 3.1908x over previous
#include <cuda_runtime.h>
#include <cuda_fp16.h>
#include <cstdint>
#include <math.h>

#define C_IN 2048
#define HWD  1024
#define PN   2048     // B*H*W
#define BB   2
#define OC   256
#define EPSV 1e-5f

#define ROWS_B2 256
#define ROWS_B3 2560
#define ROWS_B4 4864
#define ROWS_OM 7168
#define M_REAL  7924
#define M_PAD   7936

#define K2 4096       // fp16 split-K: [hi,lo] interleaved

// ---------------- scratch (static device globals; no allocation) ----------------
__device__ __half g_A2[(long)M_PAD * K2];   // 65 MB: W as [hi,lo] interleaved
__device__ __half g_B2[(long)PN * K2];      // 16.8 MB: X^T as [h,h] duplicated
__device__ float g_D[(long)M_PAD * PN];     // dense 1x1 responses
__device__ float g_OM[84 * PN];
__device__ float g_CAT[1280 * PN];
__device__ float g_FOUT[OC * PN];
__device__ float g_GAP[BB * C_IN];
__device__ float g_PV[BB * OC];

// ================= helpers =================
__device__ __forceinline__ uint32_t smem_u32(const void* p) {
    uint32_t a;
    asm("{ .reg .u64 t; cvta.to.shared.u64 t, %1; cvt.u32.u64 %0, t; }" : "=r"(a) : "l"(p));
    return a;
}
__device__ __forceinline__ void cp16(uint32_t s, const void* g) {
    asm volatile("cp.async.cg.shared.global [%0], [%1], 16;" :: "r"(s), "l"(g));
}
__device__ __forceinline__ void cp_commit() { asm volatile("cp.async.commit_group;"); }
template<int N> __device__ __forceinline__ void cp_wait() {
    asm volatile("cp.async.wait_group %0;" :: "n"(N));
}
__device__ __forceinline__ void ldsm4(uint32_t& r0, uint32_t& r1, uint32_t& r2, uint32_t& r3, uint32_t a) {
    asm volatile("ldmatrix.sync.aligned.m8n8.x4.shared.b16 {%0,%1,%2,%3}, [%4];"
                 : "=r"(r0), "=r"(r1), "=r"(r2), "=r"(r3) : "r"(a));
}
__device__ __forceinline__ void mma16816(float* c, const uint32_t* a, uint32_t b0, uint32_t b1) {
    asm volatile("mma.sync.aligned.m16n8k16.row.col.f32.f16.f16.f32 "
                 "{%0,%1,%2,%3},{%4,%5,%6,%7},{%8,%9},{%0,%1,%2,%3};"
                 : "+f"(c[0]), "+f"(c[1]), "+f"(c[2]), "+f"(c[3])
                 : "r"(a[0]), "r"(a[1]), "r"(a[2]), "r"(a[3]), "r"(b0), "r"(b1));
}
// swizzled byte offset in a 128B-row tile: col16B c, row r -> c ^= (r&7)
__device__ __forceinline__ uint32_t swz(int row, int c) {
    return (uint32_t)(row * 128 + ((c ^ (row & 7)) << 4));
}

// ================= packing =================
__global__ void pack_wA(const float* w1, const float* w2, const float* w3, const float* w4,
                        const float* wo1, const float* wm1, const float* wo2, const float* wm2,
                        const float* wo3, const float* wm3, const float* wo4, const float* wm4) {
    long idx = (long)blockIdx.x * 256 + threadIdx.x;
    if (idx >= (long)M_PAD * C_IN) return;
    int r = (int)(idx / C_IN); int c = (int)(idx % C_IN);
    float v = 0.f;
    if (r < ROWS_B2) {
        v = w1[(long)r * C_IN + c];
    } else if (r < ROWS_B3) {
        int rr = r - ROWS_B2; int t = rr >> 8; int o = rr & 255;
        v = w2[((long)o * C_IN + c) * 9 + t];
    } else if (r < ROWS_B4) {
        int rr = r - ROWS_B3; int t = rr >> 8; int o = rr & 255;
        v = w3[((long)o * C_IN + c) * 9 + t];
    } else if (r < ROWS_OM) {
        int rr = r - ROWS_B4; int t = rr >> 8; int o = rr & 255;
        v = w4[((long)o * C_IN + c) * 9 + t];
    } else if (r < M_REAL) {
        int rr = r - ROWS_OM; int m = rr / 9; int t = rr % 9;
        const float* src; int ml;
        if (m < 3)       { ml = m;      src = (ml < 2)  ? wo1 + (long)ml * C_IN * 9 : wm1 + (long)(ml - 2)  * C_IN * 9; }
        else if (m < 30) { ml = m - 3;  src = (ml < 18) ? wo2 + (long)ml * C_IN * 9 : wm2 + (long)(ml - 18) * C_IN * 9; }
        else if (m < 57) { ml = m - 30; src = (ml < 18) ? wo3 + (long)ml * C_IN * 9 : wm3 + (long)(ml - 18) * C_IN * 9; }
        else             { ml = m - 57; src = (ml < 18) ? wo4 + (long)ml * C_IN * 9 : wm4 + (long)(ml - 18) * C_IN * 9; }
        v = src[(long)c * 9 + t];
    }
    __half hi = __float2half_rn(v);
    __half lo = __float2half_rn(v - __half2float(hi));
    reinterpret_cast<__half2*>(g_A2)[idx] = __half2(hi, lo);   // -> [2*idx], [2*idx+1]
}

// transpose x[b][c][yx] -> B2[p=b*1024+yx][2c]=[2c+1]=fp16(x)
__global__ void pack_xB(const float* __restrict__ x) {
    __shared__ float t[32][33];
    int c0 = blockIdx.x * 32, yx0 = blockIdx.y * 32, b = blockIdx.z;
    int tx = threadIdx.x, ty = threadIdx.y;
    #pragma unroll
    for (int i = 0; i < 4; i++) {
        int c = c0 + ty + 8 * i;
        t[ty + 8 * i][tx] = x[((long)b * C_IN + c) * HWD + yx0 + tx];
    }
    __syncthreads();
    #pragma unroll
    for (int i = 0; i < 4; i++) {
        int yx = yx0 + ty + 8 * i;
        long p = (long)(b * HWD + yx);
        float v = t[tx][ty + 8 * i];
        __half h = __float2half_rn(v);
        reinterpret_cast<__half2*>(g_B2)[p * (K2 / 2) + c0 + tx] = __half2(h, h);
    }
}

// ================= fp16 mma.sync GEMM1: D[M][P] = A2 * B2^T =================
// CTA tile 128x128, BK=64 fp16, 3-stage cp.async, 8 warps (2M x 4N), warp tile 64x32
#define GBK 64
#define G_ITERS (K2 / GBK)      // 64
#define STG_A 16384
#define STG_SZ 32768
#define GSTAGES 3
#define GSMEM (GSTAGES * STG_SZ)   // 98304

__global__ void __launch_bounds__(256, 1) gemm1_mma() {
    extern __shared__ char smraw[];
    uint32_t sb = smem_u32(smraw);
    const int tid = threadIdx.x;
    const int lane = tid & 31, wid = tid >> 5;
    const int wm = wid & 1, wn = wid >> 1;        // 2 x 4
    const int m0 = blockIdx.y * 128, n0 = blockIdx.x * 128;
    const __half* A = g_A2;
    const __half* B = g_B2;

    float acc[4][4][4];
    #pragma unroll
    for (int i = 0; i < 4; i++)
        #pragma unroll
        for (int j = 0; j < 4; j++)
            #pragma unroll
            for (int q = 0; q < 4; q++) acc[i][j][q] = 0.f;

    auto load_stage = [&](int s) {
        uint32_t buf = sb + (uint32_t)(s % GSTAGES) * STG_SZ;
        int k0 = s * GBK;
        #pragma unroll
        for (int i = 0; i < 4; i++) {
            int t = tid + i * 256;
            int row = t >> 3, c = t & 7;
            cp16(buf + swz(row, c), A + (long)(m0 + row) * K2 + k0 + c * 8);
        }
        #pragma unroll
        for (int i = 0; i < 4; i++) {
            int t = tid + i * 256;
            int row = t >> 3, c = t & 7;
            cp16(buf + STG_A + swz(row, c), B + (long)(n0 + row) * K2 + k0 + c * 8);
        }
        cp_commit();
    };

    load_stage(0); load_stage(1); load_stage(2);

    for (int s = 0; s < G_ITERS; s++) {
        if (s < G_ITERS - 2) cp_wait<2>();
        else if (s == G_ITERS - 2) cp_wait<1>();
        else cp_wait<0>();
        __syncthreads();
        uint32_t buf = sb + (uint32_t)(s % GSTAGES) * STG_SZ;

        #pragma unroll
        for (int k16 = 0; k16 < 4; k16++) {
            uint32_t a[4][4], bfr[2][4];
            int cchunk = k16 * 2 + (lane >> 4);
            #pragma unroll
            for (int mi = 0; mi < 4; mi++) {
                int row = wm * 64 + mi * 16 + (lane & 15);
                ldsm4(a[mi][0], a[mi][1], a[mi][2], a[mi][3], buf + swz(row, cchunk));
            }
            #pragma unroll
            for (int g = 0; g < 2; g++) {
                int row = wn * 32 + g * 16 + (lane & 15);
                ldsm4(bfr[g][0], bfr[g][1], bfr[g][2], bfr[g][3], buf + STG_A + swz(row, cchunk));
            }
            #pragma unroll
            for (int mi = 0; mi < 4; mi++) {
                #pragma unroll
                for (int g = 0; g < 2; g++) {
                    mma16816(acc[mi][g * 2 + 0], a[mi], bfr[g][0], bfr[g][2]);
                    mma16816(acc[mi][g * 2 + 1], a[mi], bfr[g][1], bfr[g][3]);
                }
            }
        }
        __syncthreads();
        if (s + 3 < G_ITERS) load_stage(s + 3);
    }

    // epilogue: d0,d1 -> row l>>2, cols (l&3)*2 ; d2,d3 -> row +8
    #pragma unroll
    for (int mi = 0; mi < 4; mi++) {
        int mbase = m0 + wm * 64 + mi * 16 + (lane >> 2);
        #pragma unroll
        for (int ni = 0; ni < 4; ni++) {
            int p = n0 + wn * 32 + ni * 8 + (lane & 3) * 2;
            *reinterpret_cast<float2*>(g_D + (long)mbase * PN + p) =
                make_float2(acc[mi][ni][0], acc[mi][ni][1]);
            *reinterpret_cast<float2*>(g_D + (long)(mbase + 8) * PN + p) =
                make_float2(acc[mi][ni][2], acc[mi][ni][3]);
        }
    }
}

// ---------------- generic SGEMM (fuse conv) ----------------
template<int BM, int BN, int BK, int TM, int TN>
__global__ void sgemm(const float* __restrict__ A, const float* __restrict__ B,
                      float* __restrict__ Cc, int M, int N, int K) {
    __shared__ float As[BK * BM];
    __shared__ float Bs[BK * BN];
    const int NT = (BM / TM) * (BN / TN);
    const int tid = threadIdx.x;
    const int m0 = blockIdx.y * BM;
    const int n0 = blockIdx.x * BN;
    const int tx = tid % (BN / TN);
    const int ty = tid / (BN / TN);

    float acc[TM][TN];
    #pragma unroll
    for (int i = 0; i < TM; i++)
        #pragma unroll
        for (int j = 0; j < TN; j++) acc[i][j] = 0.f;

    for (int k0 = 0; k0 < K; k0 += BK) {
        for (int i4 = tid; i4 < BM * BK / 4; i4 += NT) {
            int row = i4 / (BK / 4);
            int cg  = i4 % (BK / 4);
            float4 v = make_float4(0.f, 0.f, 0.f, 0.f);
            if (m0 + row < M)
                v = *reinterpret_cast<const float4*>(A + (long)(m0 + row) * K + k0 + cg * 4);
            As[(cg * 4 + 0) * BM + row] = v.x;
            As[(cg * 4 + 1) * BM + row] = v.y;
            As[(cg * 4 + 2) * BM + row] = v.z;
            As[(cg * 4 + 3) * BM + row] = v.w;
        }
        for (int i4 = tid; i4 < BK * BN / 4; i4 += NT) {
            int kk  = i4 / (BN / 4);
            int col = (i4 % (BN / 4)) * 4;
            float4 v = *reinterpret_cast<const float4*>(B + (long)(k0 + kk) * N + n0 + col);
            *reinterpret_cast<float4*>(&Bs[kk * BN + col]) = v;
        }
        __syncthreads();
        #pragma unroll
        for (int kk = 0; kk < BK; kk++) {
            float af[TM], bf[TN];
            #pragma unroll
            for (int i = 0; i < TM; i++) af[i] = As[kk * BM + ty * TM + i];
            #pragma unroll
            for (int j = 0; j < TN; j++) bf[j] = Bs[kk * BN + tx * TN + j];
            #pragma unroll
            for (int i = 0; i < TM; i++)
                #pragma unroll
                for (int j = 0; j < TN; j++) acc[i][j] += af[i] * bf[j];
        }
        __syncthreads();
    }
    #pragma unroll
    for (int i = 0; i < TM; i++) {
        int m = m0 + ty * TM + i;
        if (m >= M) continue;
        #pragma unroll
        for (int j = 0; j < TN; j += 4) {
            *reinterpret_cast<float4*>(Cc + (long)m * N + n0 + tx * TN + j) =
                make_float4(acc[i][j], acc[i][j + 1], acc[i][j + 2], acc[i][j + 3]);
        }
    }
}

// ---------------- combine the 9 shifted 1x1 responses into 3x3-conv results ----------------
__global__ void om_combine() {
    int idx = blockIdx.x * 256 + threadIdx.x;
    if (idx >= 84 * PN) return;
    int m = idx >> 11; int p = idx & 2047;
    int b = p >> 10; int yx = p & 1023; int y = yx >> 5; int x = yx & 31;
    const float* E = g_D + (long)(ROWS_OM + m * 9) * PN;
    float s = 0.f;
    #pragma unroll
    for (int t = 0; t < 9; t++) {
        int yy = y + t / 3 - 1; int xx = x + t % 3 - 1;
        if (yy >= 0 && yy < 32 && xx >= 0 && xx < 32)
            s += E[(long)t * PN + b * HWD + yy * 32 + xx];
    }
    g_OM[idx] = s;
}

// ---------------- deformable sampling + modulation ----------------
__global__ void deform_combine() {
    const int kk_[4]   = {1, 3, 3, 3};
    const int dil_[4]  = {1, 6, 12, 18};
    const int pad_[4]  = {0, 6, 12, 18};
    const int drow_[4] = {0, ROWS_B2, ROWS_B3, ROWS_B4};
    const int mb_[4]   = {0, 3, 30, 57};

    int br = blockIdx.y;
    int idx = blockIdx.x * 256 + threadIdx.x;
    int o = idx >> 11; int p = idx & 2047;
    int b = p >> 10; int yx = p & 1023; int y = yx >> 5; int x = yx & 31;

    int k = kk_[br], dil = dil_[br], pad = pad_[br];
    int n = k * k;
    int hp = 32 + 2 * pad;
    float hpm1 = (float)(hp - 1);
    const float* OMB = g_OM + (long)mb_[br] * PN + p;
    const float* Db  = g_D + (long)(drow_[br] + o) * PN + b * HWD;

    float acc = 0.f;
    for (int t = 0; t < n; t++) {
        float offy = OMB[(long)t * PN];
        float offx = OMB[(long)(n + t) * PN];
        float modv = OMB[(long)(2 * n + t) * PN];
        modv = 1.f / (1.f + expf(-modv));
        float py = (float)(y + (t / k) * dil) + offy;
        float px = (float)(x + (t % k) * dil) + offx;
        py = fminf(fmaxf(py, 0.f), hpm1);
        px = fminf(fmaxf(px, 0.f), hpm1);
        float fy0 = floorf(py), fx0 = floorf(px);
        float wy = py - fy0, wx = px - fx0;
        int y0 = (int)fy0, x0 = (int)fx0;
        int y1 = min(y0 + 1, hp - 1), x1 = min(x0 + 1, hp - 1);
        const float* Dt = Db + (long)t * 256 * PN;

        float v00 = 0.f, v01 = 0.f, v10 = 0.f, v11 = 0.f;
        {
            int ry0 = y0 - pad, rx0 = x0 - pad, ry1 = y1 - pad, rx1 = x1 - pad;
            bool oy0 = (ry0 >= 0 && ry0 < 32), oy1 = (ry1 >= 0 && ry1 < 32);
            bool ox0 = (rx0 >= 0 && rx0 < 32), ox1 = (rx1 >= 0 && rx1 < 32);
            if (oy0 && ox0) v00 = Dt[ry0 * 32 + rx0];
            if (oy0 && ox1) v01 = Dt[ry0 * 32 + rx1];
            if (oy1 && ox0) v10 = Dt[ry1 * 32 + rx0];
            if (oy1 && ox1) v11 = Dt[ry1 * 32 + rx1];
        }
        float v = (1.f - wy) * ((1.f - wx) * v00 + wx * v01)
                +        wy  * ((1.f - wx) * v10 + wx * v11);
        acc += modv * v;
    }
    g_CAT[(long)(br * 256 + o) * PN + p] = acc;
}

// ---------------- reductions / BN ----------------
__device__ __forceinline__ float blockReduceSum(float v, float* sdata) {
    int tid = threadIdx.x;
    #pragma unroll
    for (int off = 16; off > 0; off >>= 1) v += __shfl_down_sync(0xffffffff, v, off);
    if ((tid & 31) == 0) sdata[tid >> 5] = v;
    __syncthreads();
    if (tid < 8) {
        float s = sdata[tid];
        #pragma unroll
        for (int off = 4; off > 0; off >>= 1) s += __shfl_down_sync(0xff, s, off);
        if (tid == 0) sdata[0] = s;
    }
    __syncthreads();
    float r = sdata[0];
    __syncthreads();
    return r;
}

__global__ void bn_relu_branches(const float* g1, const float* be1, const float* g2, const float* be2,
                                 const float* g3, const float* be3, const float* g4, const float* be4) {
    __shared__ float sdata[8];
    int ch = blockIdx.x;
    int br = ch >> 8; int c = ch & 255;
    const float* gp = br == 0 ? g1 : br == 1 ? g2 : br == 2 ? g3 : g4;
    const float* bp = br == 0 ? be1 : br == 1 ? be2 : br == 2 ? be3 : be4;
    float* row = g_CAT + (long)ch * PN;
    int tid = threadIdx.x;
    float v[8]; float s = 0.f;
    #pragma unroll
    for (int i = 0; i < 8; i++) { v[i] = row[tid + i * 256]; s += v[i]; }
    s = blockReduceSum(s, sdata);
    float mu = s / 2048.f;
    float q = 0.f;
    #pragma unroll
    for (int i = 0; i < 8; i++) { float d = v[i] - mu; q += d * d; }
    q = blockReduceSum(q, sdata);
    float inv = rsqrtf(q / 2048.f + EPSV);
    float ga = gp[c], bb = bp[c];
    #pragma unroll
    for (int i = 0; i < 8; i++)
        row[tid + i * 256] = fmaxf((v[i] - mu) * inv * ga + bb, 0.f);
}

__global__ void bn_final(const float* gf, const float* bf) {
    __shared__ float sdata[8];
    int c = blockIdx.x;
    float* row = g_FOUT + (long)c * PN;
    int tid = threadIdx.x;
    float v[8]; float s = 0.f;
    #pragma unroll
    for (int i = 0; i < 8; i++) { v[i] = row[tid + i * 256]; s += v[i]; }
    s = blockReduceSum(s, sdata);
    float mu = s / 2048.f;
    float q = 0.f;
    #pragma unroll
    for (int i = 0; i < 8; i++) { float d = v[i] - mu; q += d * d; }
    q = blockReduceSum(q, sdata);
    float inv = rsqrtf(q / 2048.f + EPSV);
    float ga = gf[c], bb = bf[c];
    #pragma unroll
    for (int i = 0; i < 8; i++)
        row[tid + i * 256] = fmaxf((v[i] - mu) * inv * ga + bb, 0.f);
}

// ---------------- pooling branch ----------------
__global__ void gap_kernel(const float* __restrict__ x) {
    __shared__ float sdata[8];
    int bc = blockIdx.x;
    const float* px = x + (long)bc * HWD;
    float s = 0.f; int tid = threadIdx.x;
    for (int i = tid; i < HWD; i += 256) s += px[i];
    s = blockReduceSum(s, sdata);
    if (tid == 0) g_GAP[bc] = s / 1024.f;
}

__global__ void pool_fc_bn(const float* __restrict__ wpool, const float* gp, const float* bp) {
    __shared__ float sdata[8];
    __shared__ float sp0;
    int o = blockIdx.x; int tid = threadIdx.x;
    const float* wr = wpool + (long)o * C_IN;
    float s0 = 0.f, s1 = 0.f;
    for (int c = tid; c < C_IN; c += 256) {
        float w = wr[c];
        s0 += w * g_GAP[c];
        s1 += w * g_GAP[2048 + c];
    }
    s0 = blockReduceSum(s0, sdata);
    if (tid == 0) sp0 = s0;
    __syncthreads();
    s1 = blockReduceSum(s1, sdata);
    if (tid == 0) {
        float p0 = sp0, p1 = s1;
        float mu = 0.5f * (p0 + p1);
        float var = 0.5f * ((p0 - mu) * (p0 - mu) + (p1 - mu) * (p1 - mu));
        float inv = rsqrtf(var + EPSV);
        float ga = gp[o], be = bp[o];
        g_PV[o]       = fmaxf((p0 - mu) * inv * ga + be, 0.f);
        g_PV[256 + o] = fmaxf((p1 - mu) * inv * ga + be, 0.f);
    }
}

__global__ void pool_broadcast() {
    int idx = blockIdx.x * 256 + threadIdx.x;
    if (idx >= OC * PN) return;
    int o = idx >> 11; int p = idx & 2047; int b = p >> 10;
    g_CAT[(long)(1024 + o) * PN + p] = g_PV[b * 256 + o];
}

// ---------------- final layout write ----------------
__global__ void writeout(float* __restrict__ out) {
    int idx = blockIdx.x * 256 + threadIdx.x;
    int b = idx >> 18; int o = (idx >> 10) & 255; int yx = idx & 1023;
    out[idx] = g_FOUT[(long)o * PN + b * HWD + yx];
}

// ---------------- launcher ----------------
extern "C" void kernel_launch(void* const* d_in, const int* in_sizes, int n_in,
                              void* d_out, int out_size) {
    (void)in_sizes; (void)n_in; (void)out_size;
    const float* x    = (const float*)d_in[0];
    const float* wo1  = (const float*)d_in[1];
    const float* wm1  = (const float*)d_in[2];
    const float* w1   = (const float*)d_in[3];
    const float* g1   = (const float*)d_in[4];
    const float* b1   = (const float*)d_in[5];
    const float* wo2  = (const float*)d_in[6];
    const float* wm2  = (const float*)d_in[7];
    const float* w2   = (const float*)d_in[8];
    const float* g2   = (const float*)d_in[9];
    const float* b2   = (const float*)d_in[10];
    const float* wo3  = (const float*)d_in[11];
    const float* wm3  = (const float*)d_in[12];
    const float* w3   = (const float*)d_in[13];
    const float* g3   = (const float*)d_in[14];
    const float* b3   = (const float*)d_in[15];
    const float* wo4  = (const float*)d_in[16];
    const float* wm4  = (const float*)d_in[17];
    const float* w4   = (const float*)d_in[18];
    const float* g4   = (const float*)d_in[19];
    const float* b4   = (const float*)d_in[20];
    const float* wpool= (const float*)d_in[21];
    const float* gp   = (const float*)d_in[22];
    const float* bp   = (const float*)d_in[23];
    const float* wfuse= (const float*)d_in[24];
    const float* gf   = (const float*)d_in[25];
    const float* bf   = (const float*)d_in[26];
    float* out = (float*)d_out;

    void *pCAT = nullptr, *pF = nullptr;
    cudaGetSymbolAddress(&pCAT, g_CAT);
    cudaGetSymbolAddress(&pF, g_FOUT);

    cudaFuncSetAttribute(gemm1_mma, cudaFuncAttributeMaxDynamicSharedMemorySize, GSMEM);

    // 1. pack weights (fp16 hi/lo interleave) + transpose input (fp16 duplicated)
    pack_wA<<<(int)(((long)M_PAD * C_IN + 255) / 256), 256>>>(w1, w2, w3, w4,
                                                              wo1, wm1, wo2, wm2, wo3, wm3, wo4, wm4);
    pack_xB<<<dim3(C_IN / 32, 32, BB), dim3(32, 8)>>>(x);

    // 2. one big fp16 tensor-core GEMM (2-pass split-fp32, K'=4096)
    gemm1_mma<<<dim3(PN / 128, M_PAD / 128), 256, GSMEM>>>();

    // 3. offset/mod 3x3 shift-sum, then bilinear deformable combine
    om_combine<<<(84 * PN + 255) / 256, 256>>>();
    deform_combine<<<dim3(2048, 4), 256>>>();

    // 4. per-branch BN + relu
    bn_relu_branches<<<1024, 256>>>(g1, b1, g2, b2, g3, b3, g4, b4);

    // 5. pooling branch
    gap_kernel<<<BB * C_IN, 256>>>(x);
    pool_fc_bn<<<256, 256>>>(wpool, gp, bp);
    pool_broadcast<<<(OC * PN) / 256, 256>>>();

    // 6. fuse 1x1 conv + final BN + relu + NCHW writeout
    sgemm<64, 64, 8, 4, 4><<<dim3(PN / 64, OC / 64), 256>>>(
        wfuse, (const float*)pCAT, (float*)pF, OC, PN, 1280);
    bn_final<<<OC, 256>>>(gf, bf);
    writeout<<<(BB * OC * HWD) / 256, 256>>>(out);
}